// round 2
// baseline (speedup 1.0000x reference)
#include <cuda_runtime.h>
#include <cuda_bf16.h>
#include <math.h>

// Problem constants
#define NEXP 64
#define TOPK 4
#define HDIM 2048
#define IDIM 1536
#define GSZ  128
#define NTOK 1024
#define CAP  128
#define A_TOT (NTOK*TOPK)        // 4096 assignments
#define HW   (HDIM/8)            // 256 packed words per gate/up row
#define IW   (IDIM/8)            // 192 packed words per down row
#define NGH  (HDIM/GSZ)          // 16 groups along H
#define NGI  (IDIM/GSZ)          // 12 groups along I

__constant__ float c_lut[16] = {0.f, 0.5f, 1.f, 1.5f, 2.f, 3.f, 4.f, 6.f,
                                -0.f,-0.5f,-1.f,-1.5f,-2.f,-3.f,-4.f,-6.f};

// Scratch (static device globals; no runtime allocation)
__device__ int   g_topk_idx[A_TOT];
__device__ float g_topk_w[A_TOT];
__device__ int   g_pos[A_TOT];
__device__ int   g_rowlist[NEXP*CAP];
__device__ int   g_count[NEXP];
__device__ float g_hbuf[(size_t)NEXP*CAP*IDIM];   // routed intermediate h
__device__ float g_hsh[(size_t)NTOK*IDIM];        // shared-expert intermediate h
__device__ float g_yrout[(size_t)NEXP*CAP*HDIM];  // routed down-proj output

// ---------------------------------------------------------------------------
// Router: logits = x @ gate_w^T; top-4 on logits (== top-4 on softmax probs),
// weights = softmax over the selected 4 (global Z cancels in tw/sum(tw)).
// Grid: NTOK/16 blocks x 256 threads. Each block: 16 tokens x 64 experts.
// ---------------------------------------------------------------------------
__global__ __launch_bounds__(256) void router_kernel(const float* __restrict__ x,
                                                     const float* __restrict__ gate_w)
{
    __shared__ float sx[16][33];
    __shared__ float sw[64][33];
    __shared__ float slog[16][65];
    int t0  = blockIdx.x * 16;
    int tid = threadIdx.x;
    int e   = tid & 63;
    int tg  = tid >> 6;          // 0..3 -> owns tokens tg*4 .. tg*4+3
    float acc[4] = {0.f, 0.f, 0.f, 0.f};

    for (int hc = 0; hc < HDIM; hc += 32) {
        __syncthreads();
#pragma unroll
        for (int k = 0; k < 8; k++) {
            int idx = tid + k * 256;
            int ee = idx >> 5, col = idx & 31;
            sw[ee][col] = gate_w[ee * HDIM + hc + col];
        }
#pragma unroll
        for (int k = 0; k < 2; k++) {
            int idx = tid + k * 256;
            int tt = idx >> 5, col = idx & 31;
            sx[tt][col] = x[(size_t)(t0 + tt) * HDIM + hc + col];
        }
        __syncthreads();
#pragma unroll 8
        for (int kk = 0; kk < 32; kk++) {
            float wv = sw[e][kk];
#pragma unroll
            for (int j = 0; j < 4; j++)
                acc[j] += sx[tg * 4 + j][kk] * wv;
        }
    }
#pragma unroll
    for (int j = 0; j < 4; j++) slog[tg * 4 + j][e] = acc[j];
    __syncthreads();

    if (tid < 16) {
        int tt = tid;
        unsigned long long used = 0ull;
        int   idxk[TOPK];
        float valk[TOPK];
#pragma unroll
        for (int k = 0; k < TOPK; k++) {
            float bv = -1e30f; int bi = 0;
            for (int ee = 0; ee < NEXP; ee++) {
                float v = slog[tt][ee];
                if (((used >> ee) & 1ull) == 0 && v > bv) { bv = v; bi = ee; }
            }
            used |= (1ull << bi);
            idxk[k] = bi; valk[k] = bv;
        }
        float s = 0.f, w[TOPK];
#pragma unroll
        for (int k = 0; k < TOPK; k++) { w[k] = expf(valk[k] - valk[0]); s += w[k]; }
#pragma unroll
        for (int k = 0; k < TOPK; k++) {
            g_topk_idx[(t0 + tt) * TOPK + k] = idxk[k];
            g_topk_w[(t0 + tt) * TOPK + k]  = w[k] / s;
        }
    }
}

__global__ void zero_counts_kernel()
{
    if (threadIdx.x < NEXP) g_count[threadIdx.x] = 0;
}

// ---------------------------------------------------------------------------
// Dispatch: pos[a] = #{a' < a : expert(a') == expert(a)}  (matches stable
// argsort semantics of the reference). Builds per-expert row lists.
// Grid: A_TOT/256 blocks x 256 threads; each block mirrors all expert ids
// into smem and each thread scans its prefix.
// ---------------------------------------------------------------------------
__global__ __launch_bounds__(256) void dispatch_kernel()
{
    __shared__ unsigned char ef[A_TOT];
    int tid = threadIdx.x;
    for (int i = tid; i < A_TOT; i += 256)
        ef[i] = (unsigned char)g_topk_idx[i];
    __syncthreads();

    int a = blockIdx.x * 256 + tid;
    int e = ef[a];
    int p = 0;
    for (int j = 0; j < a; j++) p += (ef[j] == e) ? 1 : 0;
    g_pos[a] = p;
    if (p < CAP) g_rowlist[e * CAP + p] = a;
    atomicAdd(&g_count[e], 1);
}

// ---------------------------------------------------------------------------
// GEMM1: h = silu(x Wg^T) * (x Wu^T) with on-the-fly FP4 dequant.
// Tile: 64 rows x 64 I-cols; K-chunks of 32 along H.
// ROUTED: blockIdx.x = expert, rows gathered via g_rowlist, out -> g_hbuf.
// !ROUTED: blockIdx.x = token block (64 tokens), out -> g_hsh.
// ---------------------------------------------------------------------------
template<bool ROUTED>
__global__ __launch_bounds__(256) void gemm1_kernel(
    const float* __restrict__ x,
    const int*   __restrict__ gpk, const int*   __restrict__ upk,
    const float* __restrict__ gsc, const float* __restrict__ usc)
{
    __shared__ float sX [64][33];
    __shared__ float sWg[64][33];
    __shared__ float sWu[64][33];

    int tid = threadIdx.x;
    int cx  = tid & 15;     // col thread
    int ry  = tid >> 4;     // row thread (0..15)
    int ic0 = blockIdx.y * 64;

    int n;
    const int *gp, *up; const float *gs, *us;
    if (ROUTED) {
        int e = blockIdx.x;
        n  = min(g_count[e], CAP);
        gp = gpk + (size_t)e * IDIM * HW;
        up = upk + (size_t)e * IDIM * HW;
        gs = gsc + (size_t)e * NGH * IDIM;
        us = usc + (size_t)e * NGH * IDIM;
    } else {
        n = 64; gp = gpk; up = upk; gs = gsc; us = usc;
    }
    float* hout = ROUTED ? g_hbuf : g_hsh;
    int rbase   = ROUTED ? blockIdx.x * CAP : blockIdx.x * 64;

    for (int r0 = 0; r0 < (ROUTED ? n : 64); r0 += 64) {
        int nrem = ROUTED ? (n - r0) : 64;
        float accg[4][4], accu[4][4];
#pragma unroll
        for (int i = 0; i < 4; i++)
#pragma unroll
            for (int j = 0; j < 4; j++) { accg[i][j] = 0.f; accu[i][j] = 0.f; }

        for (int hc = 0; hc < HDIM; hc += 32) {
            __syncthreads();
            {   // X tile: 64 rows x 32 cols, gathered
                int row = tid >> 2, seg = tid & 3;
                int tok;
                if (ROUTED)
                    tok = (row < nrem) ? (g_rowlist[blockIdx.x * CAP + r0 + row] >> 2) : 0;
                else
                    tok = blockIdx.x * 64 + row;
                const float4* xp = (const float4*)(x + (size_t)tok * HDIM + hc + seg * 8);
                float4 v0 = xp[0], v1 = xp[1];
                float* d = &sX[row][seg * 8];
                d[0]=v0.x; d[1]=v0.y; d[2]=v0.z; d[3]=v0.w;
                d[4]=v1.x; d[5]=v1.y; d[6]=v1.z; d[7]=v1.w;
            }
            {   // dequant gate/up weight tiles: 64 icols x 32 H
                int icol = tid >> 2, w = tid & 3;
                int i = ic0 + icol;
                unsigned wg = (unsigned)gp[i * HW + (hc >> 3) + w];
                unsigned wu = (unsigned)up[i * HW + (hc >> 3) + w];
                int grp = hc >> 7;
                float sg = gs[grp * IDIM + i];
                float su = us[grp * IDIM + i];
#pragma unroll
                for (int nb = 0; nb < 8; nb++) {
                    sWg[icol][w * 8 + nb] = c_lut[(wg >> (4 * nb)) & 15] * sg;
                    sWu[icol][w * 8 + nb] = c_lut[(wu >> (4 * nb)) & 15] * su;
                }
            }
            __syncthreads();
#pragma unroll 4
            for (int kk = 0; kk < 32; kk++) {
                float xr[4], wgv[4], wuv[4];
#pragma unroll
                for (int j = 0; j < 4; j++) xr[j] = sX[ry + 16 * j][kk];
#pragma unroll
                for (int j = 0; j < 4; j++) { wgv[j] = sWg[cx + 16 * j][kk]; wuv[j] = sWu[cx + 16 * j][kk]; }
#pragma unroll
                for (int rj = 0; rj < 4; rj++)
#pragma unroll
                    for (int cj = 0; cj < 4; cj++) {
                        accg[rj][cj] += xr[rj] * wgv[cj];
                        accu[rj][cj] += xr[rj] * wuv[cj];
                    }
            }
        }
        // epilogue: silu(g)*u
#pragma unroll
        for (int rj = 0; rj < 4; rj++) {
            int row = ry + 16 * rj;
            if (ROUTED && row >= nrem) continue;
#pragma unroll
            for (int cj = 0; cj < 4; cj++) {
                float g = accg[rj][cj], u = accu[rj][cj];
                float hv = (g / (1.f + expf(-g))) * u;
                hout[(size_t)(rbase + r0 + row) * IDIM + ic0 + cx + 16 * cj] = hv;
            }
        }
        if (!ROUTED) break;
    }
}

// ---------------------------------------------------------------------------
// GEMM2: y_rows = h @ Wd^T with FP4 dequant.
// ROUTED: out -> g_yrout (per-slot). !ROUTED: out -> y (d_out), full write.
// ---------------------------------------------------------------------------
template<bool ROUTED>
__global__ __launch_bounds__(256) void gemm2_kernel(
    const int*   __restrict__ dpk, const float* __restrict__ dsc,
    float* __restrict__ y)
{
    __shared__ float sH [64][33];
    __shared__ float sWd[64][33];

    int tid = threadIdx.x;
    int cx  = tid & 15;
    int ry  = tid >> 4;
    int oc0 = blockIdx.y * 64;

    int n; const int* dp; const float* ds;
    if (ROUTED) {
        int e = blockIdx.x;
        n  = min(g_count[e], CAP);
        dp = dpk + (size_t)e * HDIM * IW;
        ds = dsc + (size_t)e * NGI * HDIM;
    } else { n = 64; dp = dpk; ds = dsc; }

    const float* hin = ROUTED ? g_hbuf : g_hsh;
    float* yout      = ROUTED ? g_yrout : y;
    int rbase        = ROUTED ? blockIdx.x * CAP : blockIdx.x * 64;

    for (int r0 = 0; r0 < (ROUTED ? n : 64); r0 += 64) {
        int nrem = ROUTED ? (n - r0) : 64;
        float acc[4][4];
#pragma unroll
        for (int i = 0; i < 4; i++)
#pragma unroll
            for (int j = 0; j < 4; j++) acc[i][j] = 0.f;

        for (int ic = 0; ic < IDIM; ic += 32) {
            __syncthreads();
            {
                int row = tid >> 2, seg = tid & 3;
                int hr = (ROUTED && row >= nrem) ? 0 : row;
                const float4* hp = (const float4*)(hin + (size_t)(rbase + r0 + hr) * IDIM + ic + seg * 8);
                float4 v0 = hp[0], v1 = hp[1];
                float* d = &sH[row][seg * 8];
                d[0]=v0.x; d[1]=v0.y; d[2]=v0.z; d[3]=v0.w;
                d[4]=v1.x; d[5]=v1.y; d[6]=v1.z; d[7]=v1.w;
            }
            {
                int ocol = tid >> 2, w = tid & 3;
                int o = oc0 + ocol;
                unsigned wd = (unsigned)dp[o * IW + (ic >> 3) + w];
                float sd = ds[(ic >> 7) * HDIM + o];
#pragma unroll
                for (int nb = 0; nb < 8; nb++)
                    sWd[ocol][w * 8 + nb] = c_lut[(wd >> (4 * nb)) & 15] * sd;
            }
            __syncthreads();
#pragma unroll 4
            for (int kk = 0; kk < 32; kk++) {
                float hrv[4], wv[4];
#pragma unroll
                for (int j = 0; j < 4; j++) hrv[j] = sH[ry + 16 * j][kk];
#pragma unroll
                for (int j = 0; j < 4; j++) wv[j] = sWd[cx + 16 * j][kk];
#pragma unroll
                for (int rj = 0; rj < 4; rj++)
#pragma unroll
                    for (int cj = 0; cj < 4; cj++)
                        acc[rj][cj] += hrv[rj] * wv[cj];
            }
        }
#pragma unroll
        for (int rj = 0; rj < 4; rj++) {
            int row = ry + 16 * rj;
            if (ROUTED && row >= nrem) continue;
#pragma unroll
            for (int cj = 0; cj < 4; cj++)
                yout[(size_t)(rbase + r0 + row) * HDIM + oc0 + cx + 16 * cj] = acc[rj][cj];
        }
        if (!ROUTED) break;
    }
}

// ---------------------------------------------------------------------------
// Combine: y[t] += sum_k tw[t,k] * yrout[slot(t,k)]  (only valid slots).
// y already holds the shared-expert output.
// ---------------------------------------------------------------------------
__global__ __launch_bounds__(256) void combine_kernel(float* __restrict__ y)
{
    int t = blockIdx.x;
    __shared__ int   slot4[TOPK];
    __shared__ float w4[TOPK];
    int tid = threadIdx.x;
    if (tid < TOPK) {
        int a = t * TOPK + tid;
        int e = g_topk_idx[a];
        int p = g_pos[a];
        slot4[tid] = (p < CAP) ? (e * CAP + p) : -1;
        w4[tid]    = g_topk_w[a];
    }
    __syncthreads();
    for (int hh = tid; hh < HDIM; hh += 256) {
        float acc = y[(size_t)t * HDIM + hh];
#pragma unroll
        for (int k = 0; k < TOPK; k++) {
            int s = slot4[k];
            if (s >= 0) acc += w4[k] * g_yrout[(size_t)s * HDIM + hh];
        }
        y[(size_t)t * HDIM + hh] = acc;
    }
}

// ---------------------------------------------------------------------------
extern "C" void kernel_launch(void* const* d_in, const int* in_sizes, int n_in,
                              void* d_out, int out_size)
{
    const float* x              = (const float*)d_in[0];
    const float* gate_w         = (const float*)d_in[1];
    const float* gate_scales    = (const float*)d_in[2];
    const float* up_scales      = (const float*)d_in[3];
    const float* down_scales    = (const float*)d_in[4];
    const float* sh_gate_scales = (const float*)d_in[5];
    const float* sh_up_scales   = (const float*)d_in[6];
    const float* sh_down_scales = (const float*)d_in[7];
    const int*   gate_packed    = (const int*)d_in[8];
    const int*   up_packed      = (const int*)d_in[9];
    const int*   down_packed    = (const int*)d_in[10];
    const int*   sh_gate_packed = (const int*)d_in[11];
    const int*   sh_up_packed   = (const int*)d_in[12];
    const int*   sh_down_packed = (const int*)d_in[13];
    float* y = (float*)d_out;

    router_kernel<<<NTOK / 16, 256>>>(x, gate_w);
    zero_counts_kernel<<<1, 64>>>();
    dispatch_kernel<<<A_TOT / 256, 256>>>();

    // Shared expert
    gemm1_kernel<false><<<dim3(NTOK / 64, IDIM / 64), 256>>>(
        x, sh_gate_packed, sh_up_packed, sh_gate_scales, sh_up_scales);
    gemm2_kernel<false><<<dim3(NTOK / 64, HDIM / 64), 256>>>(
        sh_down_packed, sh_down_scales, y);

    // Routed experts
    gemm1_kernel<true><<<dim3(NEXP, IDIM / 64), 256>>>(
        x, gate_packed, up_packed, gate_scales, up_scales);
    gemm2_kernel<true><<<dim3(NEXP, HDIM / 64), 256>>>(
        down_packed, down_scales, y);

    // Combine routed contributions into y
    combine_kernel<<<NTOK, 256>>>(y);
}

// round 3
// speedup vs baseline: 6.7148x; 6.7148x over previous
#include <cuda_runtime.h>
#include <cuda_fp16.h>
#include <math.h>

// Problem constants
#define NEXP 64
#define TOPK 4
#define HDIM 2048
#define IDIM 1536
#define GSZ  128
#define NTOK 1024
#define CAP  128
#define A_TOT (NTOK*TOPK)        // 4096 assignments
#define HW   (HDIM/8)            // 256 packed words per gate/up row
#define IW   (IDIM/8)            // 192 packed words per down row
#define NGH  (HDIM/GSZ)          // 16 groups along H
#define NGI  (IDIM/GSZ)          // 12 groups along I

// Scratch (static device globals; no runtime allocation)
__device__ int    g_topk_idx[A_TOT];
__device__ float  g_topk_w[A_TOT];
__device__ int    g_pos[A_TOT];
__device__ int    g_rowlist[NEXP*CAP];
__device__ int    g_count[NEXP];
__device__ __half g_xh[(size_t)NTOK*HDIM];          // x in fp16
__device__ __half g_hbh[(size_t)NEXP*CAP*IDIM];     // routed h (fp16)
__device__ __half g_hshh[(size_t)NTOK*IDIM];        // shared h (fp16)
__device__ float  g_yrout[(size_t)NEXP*CAP*HDIM];   // routed down output

// ---------------------------------------------------------------------------
// helpers
// ---------------------------------------------------------------------------
__device__ __forceinline__ unsigned sptr(const void* p) {
    return (unsigned)__cvta_generic_to_shared(p);
}

__device__ __forceinline__ void ldsm4(unsigned a, unsigned& r0, unsigned& r1,
                                      unsigned& r2, unsigned& r3) {
    asm volatile("ldmatrix.sync.aligned.m8n8.x4.shared.b16 {%0,%1,%2,%3}, [%4];"
                 : "=r"(r0), "=r"(r1), "=r"(r2), "=r"(r3) : "r"(a));
}

__device__ __forceinline__ void mma16816(float* c, const unsigned* a,
                                         unsigned b0, unsigned b1) {
    asm volatile("mma.sync.aligned.m16n8k16.row.col.f32.f16.f16.f32 "
                 "{%0,%1,%2,%3},{%4,%5,%6,%7},{%8,%9},{%0,%1,%2,%3};"
                 : "+f"(c[0]), "+f"(c[1]), "+f"(c[2]), "+f"(c[3])
                 : "r"(a[0]), "r"(a[1]), "r"(a[2]), "r"(a[3]), "r"(b0), "r"(b1));
}

// FP4 e2m1 nibble b -> fp16 bits ((b&7)<<9 | (b&8)<<12), value = fp16 * 2^14.
// Scale passed in pre-multiplied by 2^14. Produces 4 half2 (k-pairs 01,23,45,67).
__device__ __forceinline__ void dq8(unsigned w, __half2 s, unsigned* o) {
    unsigned lo = w & 0x0F0F0F0Fu;          // nibbles 0,2,4,6
    unsigned hi = (w >> 4) & 0x0F0F0F0Fu;   // nibbles 1,3,5,7
    unsigned fl = ((lo << 1) & 0x0E0E0E0Eu) | ((lo << 4) & 0x80808080u);
    unsigned fh = ((hi << 1) & 0x0E0E0E0Eu) | ((hi << 4) & 0x80808080u);
    unsigned m0 = __byte_perm(fl, fh, 0x5140);  // [f0,f1,f2,f3] bytes for nib 0..3
    unsigned m1 = __byte_perm(fl, fh, 0x7362);  // nib 4..7
    unsigned t0 = __byte_perm(m0, 0, 0x1404);   // [0,f0,0,f1]
    unsigned t1 = __byte_perm(m0, 0, 0x3424);   // [0,f2,0,f3]
    unsigned t2 = __byte_perm(m1, 0, 0x1404);
    unsigned t3 = __byte_perm(m1, 0, 0x3424);
    __half2 h0 = __hmul2(*reinterpret_cast<__half2*>(&t0), s);
    __half2 h1 = __hmul2(*reinterpret_cast<__half2*>(&t1), s);
    __half2 h2 = __hmul2(*reinterpret_cast<__half2*>(&t2), s);
    __half2 h3 = __hmul2(*reinterpret_cast<__half2*>(&t3), s);
    o[0] = *reinterpret_cast<unsigned*>(&h0);
    o[1] = *reinterpret_cast<unsigned*>(&h1);
    o[2] = *reinterpret_cast<unsigned*>(&h2);
    o[3] = *reinterpret_cast<unsigned*>(&h3);
}

__device__ __forceinline__ float silu_f(float v) {
    return v / (1.f + expf(-v));
}

// ---------------------------------------------------------------------------
// x -> fp16
// ---------------------------------------------------------------------------
__global__ __launch_bounds__(256) void xcvt_kernel(const float* __restrict__ x)
{
    size_t i = ((size_t)blockIdx.x * 256 + threadIdx.x) * 4;
    float4 v = *(const float4*)(x + i);
    __half2 a = __floats2half2_rn(v.x, v.y);
    __half2 b = __floats2half2_rn(v.z, v.w);
    *(__half2*)&g_xh[i]     = a;
    *(__half2*)&g_xh[i + 2] = b;
}

// ---------------------------------------------------------------------------
// Router (fp32, exact top-k): logits = x @ gate_w^T; weights = softmax over
// the selected 4 (global partition cancels).
// ---------------------------------------------------------------------------
__global__ __launch_bounds__(256) void router_kernel(const float* __restrict__ x,
                                                     const float* __restrict__ gate_w)
{
    __shared__ float sx[16][33];
    __shared__ float sw[64][33];
    __shared__ float slog[16][65];
    int t0  = blockIdx.x * 16;
    int tid = threadIdx.x;
    int e   = tid & 63;
    int tg  = tid >> 6;
    float acc[4] = {0.f, 0.f, 0.f, 0.f};

    for (int hc = 0; hc < HDIM; hc += 32) {
        __syncthreads();
#pragma unroll
        for (int k = 0; k < 8; k++) {
            int idx = tid + k * 256;
            sw[idx >> 5][idx & 31] = gate_w[(idx >> 5) * HDIM + hc + (idx & 31)];
        }
#pragma unroll
        for (int k = 0; k < 2; k++) {
            int idx = tid + k * 256;
            sx[idx >> 5][idx & 31] = x[(size_t)(t0 + (idx >> 5)) * HDIM + hc + (idx & 31)];
        }
        __syncthreads();
#pragma unroll 8
        for (int kk = 0; kk < 32; kk++) {
            float wv = sw[e][kk];
#pragma unroll
            for (int j = 0; j < 4; j++) acc[j] += sx[tg * 4 + j][kk] * wv;
        }
    }
#pragma unroll
    for (int j = 0; j < 4; j++) slog[tg * 4 + j][e] = acc[j];
    __syncthreads();

    if (tid < 16) {
        int tt = tid;
        unsigned long long used = 0ull;
        int idxk[TOPK]; float valk[TOPK];
#pragma unroll
        for (int k = 0; k < TOPK; k++) {
            float bv = -1e30f; int bi = 0;
            for (int ee = 0; ee < NEXP; ee++) {
                float v = slog[tt][ee];
                if (((used >> ee) & 1ull) == 0 && v > bv) { bv = v; bi = ee; }
            }
            used |= (1ull << bi);
            idxk[k] = bi; valk[k] = bv;
        }
        float s = 0.f, w[TOPK];
#pragma unroll
        for (int k = 0; k < TOPK; k++) { w[k] = expf(valk[k] - valk[0]); s += w[k]; }
#pragma unroll
        for (int k = 0; k < TOPK; k++) {
            g_topk_idx[(t0 + tt) * TOPK + k] = idxk[k];
            g_topk_w[(t0 + tt) * TOPK + k]  = w[k] / s;
        }
    }
}

__global__ void zero_counts_kernel()
{
    if (threadIdx.x < NEXP) g_count[threadIdx.x] = 0;
}

// ---------------------------------------------------------------------------
// Dispatch: pos[a] = #{a' < a : expert(a') == expert(a)}
// ---------------------------------------------------------------------------
__global__ __launch_bounds__(256) void dispatch_kernel()
{
    __shared__ unsigned char ef[A_TOT];
    int tid = threadIdx.x;
    for (int i = tid; i < A_TOT; i += 256)
        ef[i] = (unsigned char)g_topk_idx[i];
    __syncthreads();

    int a = blockIdx.x * 256 + tid;
    int e = ef[a];
    int p = 0;
    for (int j = 0; j < a; j++) p += (ef[j] == e) ? 1 : 0;
    g_pos[a] = p;
    if (p < CAP) g_rowlist[e * CAP + p] = a;
    atomicAdd(&g_count[e], 1);
}

// ---------------------------------------------------------------------------
// GEMM1 (tensor cores): h = silu(x Wg^T) * (x Wu^T), FP4 dequant to fp16.
// Block tile 64(M) x 64(N), K-chunk 64, 8 warps (2M x 4N of 32x16 warp tiles).
// ---------------------------------------------------------------------------
template<bool ROUTED>
__global__ __launch_bounds__(256) void gemm1_mma(
    const int* __restrict__ gpk, const int* __restrict__ upk,
    const float* __restrict__ gsc, const float* __restrict__ usc)
{
    __shared__ __half sX [64][72];
    __shared__ __half sWg[64][72];
    __shared__ __half sWu[64][72];
    __shared__ int srows[64];

    int tid = threadIdx.x;
    int ic0 = blockIdx.y * 64;
    int e   = blockIdx.x;

    int n; const int *gp, *up; const float *gs, *us;
    if (ROUTED) {
        n  = min(g_count[e], CAP);
        gp = gpk + (size_t)e * IDIM * HW;
        up = upk + (size_t)e * IDIM * HW;
        gs = gsc + (size_t)e * NGH * IDIM;
        us = usc + (size_t)e * NGH * IDIM;
    } else { n = 64; gp = gpk; up = upk; gs = gsc; us = usc; }

    __half* hout = ROUTED ? g_hbh : g_hshh;
    int rbase    = ROUTED ? e * CAP : e * 64;

    int w = tid >> 5, l = tid & 31;
    int mb = (w & 1) * 32, nb = (w >> 1) * 16;
    int xrow = tid >> 2, xseg = tid & 3;
    int i_w = ic0 + xrow;

    for (int r0 = 0; r0 < n; r0 += 64) {
        int nrem = ROUTED ? (n - r0) : 64;
        __syncthreads();
        if (ROUTED && tid < 64)
            srows[tid] = (r0 + tid < n) ? (g_rowlist[e * CAP + r0 + tid] >> 2) : 0;
        __syncthreads();

        float accg[2][2][4], accu[2][2][4];
#pragma unroll
        for (int i = 0; i < 2; i++)
#pragma unroll
            for (int j = 0; j < 2; j++)
#pragma unroll
                for (int q = 0; q < 4; q++) { accg[i][j][q] = 0.f; accu[i][j][q] = 0.f; }

        int tok;
        if (ROUTED) tok = srows[min(xrow, nrem - 1)];
        else        tok = e * 64 + xrow;

        uint4 xa, xb; int2 gw, uw; float sgf, suf;
        auto LOAD = [&](int kc) {
            const uint4* xp = (const uint4*)(g_xh + (size_t)tok * HDIM + kc + xseg * 16);
            xa = xp[0]; xb = xp[1];
            gw = ((const int2*)(gp + (size_t)i_w * HW + (kc >> 3)))[xseg];
            uw = ((const int2*)(up + (size_t)i_w * HW + (kc >> 3)))[xseg];
            int grp = kc >> 7;
            sgf = gs[grp * IDIM + i_w];
            suf = us[grp * IDIM + i_w];
        };
        auto STORE = [&]() {
            *(uint4*)&sX[xrow][xseg * 16]     = xa;
            *(uint4*)&sX[xrow][xseg * 16 + 8] = xb;
            __half2 s2g = __float2half2_rn(sgf * 16384.f);
            __half2 s2u = __float2half2_rn(suf * 16384.f);
            unsigned o[4];
            dq8((unsigned)gw.x, s2g, o);
            *(uint2*)&sWg[xrow][xseg * 16]      = make_uint2(o[0], o[1]);
            *(uint2*)&sWg[xrow][xseg * 16 + 4]  = make_uint2(o[2], o[3]);
            dq8((unsigned)gw.y, s2g, o);
            *(uint2*)&sWg[xrow][xseg * 16 + 8]  = make_uint2(o[0], o[1]);
            *(uint2*)&sWg[xrow][xseg * 16 + 12] = make_uint2(o[2], o[3]);
            dq8((unsigned)uw.x, s2u, o);
            *(uint2*)&sWu[xrow][xseg * 16]      = make_uint2(o[0], o[1]);
            *(uint2*)&sWu[xrow][xseg * 16 + 4]  = make_uint2(o[2], o[3]);
            dq8((unsigned)uw.y, s2u, o);
            *(uint2*)&sWu[xrow][xseg * 16 + 8]  = make_uint2(o[0], o[1]);
            *(uint2*)&sWu[xrow][xseg * 16 + 12] = make_uint2(o[2], o[3]);
        };

        LOAD(0);
        for (int c = 0; c < HDIM / 64; c++) {
            __syncthreads();
            STORE();
            __syncthreads();
            if (c + 1 < HDIM / 64) LOAD((c + 1) * 64);
#pragma unroll
            for (int ks = 0; ks < 4; ks++) {
                int k0 = ks * 16;
                unsigned a0[4], a1[4], bg[4], bu[4];
                ldsm4(sptr(&sX[mb      + (l & 7) + ((l >> 3) & 1) * 8][k0 + (l >> 4) * 8]),
                      a0[0], a0[1], a0[2], a0[3]);
                ldsm4(sptr(&sX[mb + 16 + (l & 7) + ((l >> 3) & 1) * 8][k0 + (l >> 4) * 8]),
                      a1[0], a1[1], a1[2], a1[3]);
                ldsm4(sptr(&sWg[nb + ((l >> 4) << 3) + (l & 7)][k0 + ((l >> 3) & 1) * 8]),
                      bg[0], bg[1], bg[2], bg[3]);
                ldsm4(sptr(&sWu[nb + ((l >> 4) << 3) + (l & 7)][k0 + ((l >> 3) & 1) * 8]),
                      bu[0], bu[1], bu[2], bu[3]);
                mma16816(accg[0][0], a0, bg[0], bg[1]);
                mma16816(accg[0][1], a0, bg[2], bg[3]);
                mma16816(accg[1][0], a1, bg[0], bg[1]);
                mma16816(accg[1][1], a1, bg[2], bg[3]);
                mma16816(accu[0][0], a0, bu[0], bu[1]);
                mma16816(accu[0][1], a0, bu[2], bu[3]);
                mma16816(accu[1][0], a1, bu[0], bu[1]);
                mma16816(accu[1][1], a1, bu[2], bu[3]);
            }
        }

        // epilogue: silu(g)*u -> fp16
        int qm = l >> 2, qn = (l & 3) * 2;
#pragma unroll
        for (int mi = 0; mi < 2; mi++)
#pragma unroll
            for (int ni = 0; ni < 2; ni++) {
                int lr   = mb + mi * 16 + qm;
                int icol = ic0 + nb + ni * 8 + qn;
                float* g4 = accg[mi][ni]; float* u4 = accu[mi][ni];
                if (!ROUTED || lr < nrem) {
                    float h0 = silu_f(g4[0]) * u4[0];
                    float h1 = silu_f(g4[1]) * u4[1];
                    *(__half2*)&hout[(size_t)(rbase + r0 + lr) * IDIM + icol] =
                        __floats2half2_rn(h0, h1);
                }
                if (!ROUTED || lr + 8 < nrem) {
                    float h2 = silu_f(g4[2]) * u4[2];
                    float h3 = silu_f(g4[3]) * u4[3];
                    *(__half2*)&hout[(size_t)(rbase + r0 + lr + 8) * IDIM + icol] =
                        __floats2half2_rn(h2, h3);
                }
            }
        if (!ROUTED) break;
    }
}

// ---------------------------------------------------------------------------
// GEMM2 (tensor cores): y = h @ Wd^T, FP4 dequant to fp16, fp32 out.
// ---------------------------------------------------------------------------
template<bool ROUTED>
__global__ __launch_bounds__(256) void gemm2_mma(
    const int* __restrict__ dpk, const float* __restrict__ dsc,
    float* __restrict__ y)
{
    __shared__ __half sH[64][72];
    __shared__ __half sW[64][72];

    int tid = threadIdx.x;
    int oc0 = blockIdx.y * 64;
    int e   = blockIdx.x;

    int n; const int* dp; const float* ds;
    if (ROUTED) {
        n  = min(g_count[e], CAP);
        dp = dpk + (size_t)e * HDIM * IW;
        ds = dsc + (size_t)e * NGI * HDIM;
    } else { n = 64; dp = dpk; ds = dsc; }

    const __half* hin = ROUTED ? g_hbh : g_hshh;
    float* yout       = ROUTED ? g_yrout : y;
    int rbase         = ROUTED ? e * CAP : e * 64;

    int w = tid >> 5, l = tid & 31;
    int mb = (w & 1) * 32, nb = (w >> 1) * 16;
    int xrow = tid >> 2, xseg = tid & 3;
    int o_w = oc0 + xrow;

    for (int r0 = 0; r0 < n; r0 += 64) {
        int nrem = ROUTED ? (n - r0) : 64;
        int hr = rbase + r0 + (ROUTED ? min(xrow, nrem - 1) : xrow);

        float acc[2][2][4];
#pragma unroll
        for (int i = 0; i < 2; i++)
#pragma unroll
            for (int j = 0; j < 2; j++)
#pragma unroll
                for (int q = 0; q < 4; q++) acc[i][j][q] = 0.f;

        uint4 ha, hb; int2 dw; float sdf;
        auto LOAD = [&](int kc) {
            const uint4* hp = (const uint4*)(hin + (size_t)hr * IDIM + kc + xseg * 16);
            ha = hp[0]; hb = hp[1];
            dw = ((const int2*)(dp + (size_t)o_w * IW + (kc >> 3)))[xseg];
            sdf = ds[(kc >> 7) * HDIM + o_w];
        };
        auto STORE = [&]() {
            *(uint4*)&sH[xrow][xseg * 16]     = ha;
            *(uint4*)&sH[xrow][xseg * 16 + 8] = hb;
            __half2 s2 = __float2half2_rn(sdf * 16384.f);
            unsigned o[4];
            dq8((unsigned)dw.x, s2, o);
            *(uint2*)&sW[xrow][xseg * 16]      = make_uint2(o[0], o[1]);
            *(uint2*)&sW[xrow][xseg * 16 + 4]  = make_uint2(o[2], o[3]);
            dq8((unsigned)dw.y, s2, o);
            *(uint2*)&sW[xrow][xseg * 16 + 8]  = make_uint2(o[0], o[1]);
            *(uint2*)&sW[xrow][xseg * 16 + 12] = make_uint2(o[2], o[3]);
        };

        LOAD(0);
        for (int c = 0; c < IDIM / 64; c++) {
            __syncthreads();
            STORE();
            __syncthreads();
            if (c + 1 < IDIM / 64) LOAD((c + 1) * 64);
#pragma unroll
            for (int ks = 0; ks < 4; ks++) {
                int k0 = ks * 16;
                unsigned a0[4], a1[4], bw[4];
                ldsm4(sptr(&sH[mb      + (l & 7) + ((l >> 3) & 1) * 8][k0 + (l >> 4) * 8]),
                      a0[0], a0[1], a0[2], a0[3]);
                ldsm4(sptr(&sH[mb + 16 + (l & 7) + ((l >> 3) & 1) * 8][k0 + (l >> 4) * 8]),
                      a1[0], a1[1], a1[2], a1[3]);
                ldsm4(sptr(&sW[nb + ((l >> 4) << 3) + (l & 7)][k0 + ((l >> 3) & 1) * 8]),
                      bw[0], bw[1], bw[2], bw[3]);
                mma16816(acc[0][0], a0, bw[0], bw[1]);
                mma16816(acc[0][1], a0, bw[2], bw[3]);
                mma16816(acc[1][0], a1, bw[0], bw[1]);
                mma16816(acc[1][1], a1, bw[2], bw[3]);
            }
        }
        __syncthreads();   // protect smem before next r0 iteration refill

        int qm = l >> 2, qn = (l & 3) * 2;
#pragma unroll
        for (int mi = 0; mi < 2; mi++)
#pragma unroll
            for (int ni = 0; ni < 2; ni++) {
                int lr   = mb + mi * 16 + qm;
                int ocol = oc0 + nb + ni * 8 + qn;
                float* c4 = acc[mi][ni];
                if (!ROUTED || lr < nrem) {
                    *(float2*)&yout[(size_t)(rbase + r0 + lr) * HDIM + ocol] =
                        make_float2(c4[0], c4[1]);
                }
                if (!ROUTED || lr + 8 < nrem) {
                    *(float2*)&yout[(size_t)(rbase + r0 + lr + 8) * HDIM + ocol] =
                        make_float2(c4[2], c4[3]);
                }
            }
        if (!ROUTED) break;
    }
}

// ---------------------------------------------------------------------------
// Combine: y[t] += sum_k tw[t,k] * yrout[slot(t,k)]
// ---------------------------------------------------------------------------
__global__ __launch_bounds__(256) void combine_kernel(float* __restrict__ y)
{
    int t = blockIdx.x;
    __shared__ int   slot4[TOPK];
    __shared__ float w4[TOPK];
    int tid = threadIdx.x;
    if (tid < TOPK) {
        int a = t * TOPK + tid;
        int e = g_topk_idx[a];
        int p = g_pos[a];
        slot4[tid] = (p < CAP) ? (e * CAP + p) : -1;
        w4[tid]    = g_topk_w[a];
    }
    __syncthreads();
    for (int hh = tid; hh < HDIM; hh += 256) {
        float acc = y[(size_t)t * HDIM + hh];
#pragma unroll
        for (int k = 0; k < TOPK; k++) {
            int s = slot4[k];
            if (s >= 0) acc += w4[k] * g_yrout[(size_t)s * HDIM + hh];
        }
        y[(size_t)t * HDIM + hh] = acc;
    }
}

// ---------------------------------------------------------------------------
extern "C" void kernel_launch(void* const* d_in, const int* in_sizes, int n_in,
                              void* d_out, int out_size)
{
    const float* x              = (const float*)d_in[0];
    const float* gate_w         = (const float*)d_in[1];
    const float* gate_scales    = (const float*)d_in[2];
    const float* up_scales      = (const float*)d_in[3];
    const float* down_scales    = (const float*)d_in[4];
    const float* sh_gate_scales = (const float*)d_in[5];
    const float* sh_up_scales   = (const float*)d_in[6];
    const float* sh_down_scales = (const float*)d_in[7];
    const int*   gate_packed    = (const int*)d_in[8];
    const int*   up_packed      = (const int*)d_in[9];
    const int*   down_packed    = (const int*)d_in[10];
    const int*   sh_gate_packed = (const int*)d_in[11];
    const int*   sh_up_packed   = (const int*)d_in[12];
    const int*   sh_down_packed = (const int*)d_in[13];
    float* y = (float*)d_out;

    xcvt_kernel<<<NTOK * HDIM / 1024, 256>>>(x);
    router_kernel<<<NTOK / 16, 256>>>(x, gate_w);
    zero_counts_kernel<<<1, 64>>>();
    dispatch_kernel<<<A_TOT / 256, 256>>>();

    // Shared expert
    gemm1_mma<false><<<dim3(NTOK / 64, IDIM / 64), 256>>>(
        sh_gate_packed, sh_up_packed, sh_gate_scales, sh_up_scales);
    gemm2_mma<false><<<dim3(NTOK / 64, HDIM / 64), 256>>>(
        sh_down_packed, sh_down_scales, y);

    // Routed experts
    gemm1_mma<true><<<dim3(NEXP, IDIM / 64), 256>>>(
        gate_packed, up_packed, gate_scales, up_scales);
    gemm2_mma<true><<<dim3(NEXP, HDIM / 64), 256>>>(
        down_packed, down_scales, y);

    combine_kernel<<<NTOK, 256>>>(y);
}